// round 16
// baseline (speedup 1.0000x reference)
#include <cuda_runtime.h>
#include <cuda_bf16.h>
#include <cuda_fp16.h>
#include <cstdint>

// Problem constants (fixed shapes)
#define NHEAD 8
#define DH    64
#define HW_   128
#define NPIX  65536      // B*H*W
#define CCH   512        // channels

typedef unsigned long long u64;
typedef unsigned int u32;

// ---- scratch (allocation-free rule: __device__ globals) --------------------
__device__ __half g_xh[(size_t)NPIX * CCH];          // X (fp16), [pixel][channel]
__device__ __half g_w16[CCH * CCH];                  // W fp16, row-major [m][k]
__device__ float g_bias[NHEAD * 64 * 64];            // [head][q][k]
__device__ u32   g_ctr[4];                           // per-batch attn-done counters

// ---- family-portable PTX helpers ------------------------------------------
__device__ __forceinline__ u32 smem_u32(const void* p) {
    u32 a; asm("{ .reg .u64 t; cvta.to.shared.u64 t, %1; cvt.u32.u64 %0, t; }"
               : "=r"(a) : "l"(p));
    return a;
}
__device__ __forceinline__ void cpa16(u32 dst, const void* src) {
    asm volatile("cp.async.cg.shared.global [%0], [%1], 16;" :: "r"(dst), "l"(src));
}
#define CPA_COMMIT() asm volatile("cp.async.commit_group;" ::: "memory")
#define CPA_WAIT(n)  asm volatile("cp.async.wait_group %0;" :: "n"(n) : "memory")

__device__ __forceinline__ void ldmx4(u32* r, u32 addr) {
    asm volatile("ldmatrix.sync.aligned.m8n8.x4.shared.b16 {%0,%1,%2,%3}, [%4];"
        : "=r"(r[0]), "=r"(r[1]), "=r"(r[2]), "=r"(r[3]) : "r"(addr));
}
__device__ __forceinline__ void ldmx2(u32* r, u32 addr) {
    asm volatile("ldmatrix.sync.aligned.m8n8.x2.shared.b16 {%0,%1}, [%2];"
        : "=r"(r[0]), "=r"(r[1]) : "r"(addr));
}
__device__ __forceinline__ void ldmx4t(u32* r, u32 addr) {
    asm volatile("ldmatrix.sync.aligned.m8n8.x4.trans.shared.b16 {%0,%1,%2,%3}, [%4];"
        : "=r"(r[0]), "=r"(r[1]), "=r"(r[2]), "=r"(r[3]) : "r"(addr));
}
// bf16 mma (attention QK)
__device__ __forceinline__ void mma16816(float* c, const u32* a, const u32* b) {
    asm volatile("mma.sync.aligned.m16n8k16.row.col.f32.bf16.bf16.f32 "
        "{%0,%1,%2,%3}, {%4,%5,%6,%7}, {%8,%9}, {%0,%1,%2,%3};"
        : "+f"(c[0]), "+f"(c[1]), "+f"(c[2]), "+f"(c[3])
        : "r"(a[0]), "r"(a[1]), "r"(a[2]), "r"(a[3]), "r"(b[0]), "r"(b[1]));
}
// fp16 mma (projection + attention PV)
__device__ __forceinline__ void mma16816h(float* c, const u32* a, const u32* b) {
    asm volatile("mma.sync.aligned.m16n8k16.row.col.f32.f16.f16.f32 "
        "{%0,%1,%2,%3}, {%4,%5,%6,%7}, {%8,%9}, {%0,%1,%2,%3};"
        : "+f"(c[0]), "+f"(c[1]), "+f"(c[2]), "+f"(c[3])
        : "r"(a[0]), "r"(a[1]), "r"(a[2]), "r"(a[3]), "r"(b[0]), "r"(b[1]));
}
// pack two fp32 -> bf16 pair (hi/lo split)
__device__ __forceinline__ void bfsplit2(float x0, float x1, u32& h, u32& l) {
    __nv_bfloat16 h0 = __float2bfloat16(x0);
    __nv_bfloat16 h1 = __float2bfloat16(x1);
    __nv_bfloat16 l0 = __float2bfloat16(x0 - __bfloat162float(h0));
    __nv_bfloat16 l1 = __float2bfloat16(x1 - __bfloat162float(h1));
    h = (u32)__bfloat16_as_ushort(h0) | ((u32)__bfloat16_as_ushort(h1) << 16);
    l = (u32)__bfloat16_as_ushort(l0) | ((u32)__bfloat16_as_ushort(l1) << 16);
}
// pack two fp32 -> fp16 pair
__device__ __forceinline__ u32 hpack2(float x0, float x1) {
    __half2 h = __floats2half2_rn(x0, x1);
    return *(u32*)&h;
}

// XOR-swizzled 64x64 b16 tile: row*128B, 8 chunks of 16B, chunk ^= row&7.
#define SWZ(row, col) (((row) << 7) + (((((col) >> 3) ^ (row)) & 7) << 4) + (((col) & 7) << 1))

// ---------------------------------------------------------------------------
// Kernel: fused prep — W->fp16, bias expand, counter reset.
// ---------------------------------------------------------------------------
__global__ void __launch_bounds__(256) prep_kernel(const float* __restrict__ W,
                                                   const float* __restrict__ rpb,
                                                   const int* __restrict__ rel) {
    int idx = blockIdx.x * 256 + threadIdx.x;
    if (idx < 4) g_ctr[idx] = 0u;
    if (idx < CCH * CCH) {
        g_w16[idx] = __float2half_rn(W[idx]);
    } else {
        int i = idx - CCH * CCH;                    // 0..32767
        int h = i >> 12;
        int r = i & 4095;                           // q*64 + k
        g_bias[i] = rpb[rel[r] * NHEAD + h];
    }
}

// ---------------------------------------------------------------------------
// attn smem layout (42496 bytes)
// ---------------------------------------------------------------------------
#define QH_O  0              // fp32 q staging = [0, 16384)
#define QL_O  8192
#define KH_O  16384          // fp32 k staging = [16384, 32768)
#define KL_O  24576
#define VH_O  32768          // fp16 V tile [a][d], 8KB
#define PSQ_O 40960          // 128 floats
#define PSK_O 41472          // 128 floats
#define QSV_O 41984          // 64 floats
#define KSV_O 42240          // 64 floats
#define FUSED_SMEM 42496

// proj smem layout (2 stages x 15360 = 30720 bytes; fits in FUSED_SMEM)
#define LDT3 40                      // 32 + 8 pad (fp16 units)
#define PW_B (128 * LDT3 * 2)        // 10240 bytes (W tile 128 x 32)
#define PX_B (64 * LDT3 * 2)         // 5120 bytes  (X tile 64 x 32)
#define PSTG3 (PW_B + PX_B)          // 15360

__device__ __forceinline__ void proj_load_stage3(u32 sbase, int m0g, int n0g, int k0, int tid) {
    #pragma unroll
    for (int j = 0; j < 4; j++) {                 // W: 512 x 16B chunks
        int id = tid + j * 128;
        int r  = id >> 2;                         // 0..127
        int c  = (id & 3) * 8;
        cpa16(sbase + 2 * (r * LDT3 + c), g_w16 + (size_t)(m0g + r) * CCH + k0 + c);
    }
    #pragma unroll
    for (int j = 0; j < 2; j++) {                 // X: 256 x 16B chunks
        int id = tid + j * 128;
        int r  = id >> 2;                         // 0..63
        int c  = (id & 3) * 8;
        cpa16(sbase + PW_B + 2 * (r * LDT3 + c), g_xh + (size_t)(n0g + r) * CCH + k0 + c);
    }
    CPA_COMMIT();
}

// ---------------------------------------------------------------------------
// Fused kernel with INTERLEAVED bid segments:
//   A0(2048) A1(2048) P0(1024) A2(2048) P1(1024) A3(2048) P2(1024) P3(1024)
// Proj segment for batch b sits after all attn blocks of batch b, but BEFORE
// attn of later batches -> proj b overlaps attn b+2.
// __launch_bounds__(128,5): both paths at 5 CTA/SM (96 regs measured).
// ---------------------------------------------------------------------------
__global__ void __launch_bounds__(128, 5) fused_kernel(const float* __restrict__ qkv,
                                                       const float* __restrict__ lscale,
                                                       const float* __restrict__ pb,
                                                       float* __restrict__ out) {
    extern __shared__ char smem[];
    const int tid  = threadIdx.x;
    const int lane = tid & 31;
    const int wrp  = tid >> 5;
    const u32 sb = smem_u32(smem);

    // ---- bid -> (role, index) mapping ----
    const int bid = blockIdx.x;
    int aid = -1, pid = -1;
    if      (bid <  4096) aid = bid;                   // A0, A1
    else if (bid <  5120) pid = bid - 4096;            // P0
    else if (bid <  7168) aid = bid - 1024;            // A2
    else if (bid <  8192) pid = bid - 7168 + 1024;     // P1
    else if (bid < 10240) aid = bid - 2048;            // A3
    else if (bid < 11264) pid = bid - 10240 + 2048;    // P2
    else                  pid = bid - 11264 + 3072;    // P3

    if (aid >= 0) {
        // ================= ATTENTION =================
        float* psq  = (float*)(smem + PSQ_O);
        float* psk  = (float*)(smem + PSK_O);
        float* qsv  = (float*)(smem + QSV_O);
        float* ksv  = (float*)(smem + KSV_O);

        const int wh   = aid;
        const int head = wh & 7;
        const int win  = wh >> 3;
        const int b    = win >> 8;
        const int wy   = (win >> 4) & 15;
        const int wx   = win & 15;

        const float* base = qkv + (size_t)b * (NHEAD * 192 * 16384)
                                + (size_t)head * (192 * 16384)
                                + wy * 8 * HW_ + wx * 8;

        // ---- issue q,k as cp.async (2 groups) ----
        #pragma unroll
        for (int kind = 0; kind < 2; kind++) {
            #pragma unroll
            for (int j = 0; j < 8; j++) {
                int id = tid + j * 128;
                int d  = id >> 4;
                int ay = (id >> 1) & 7;
                int hf = id & 1;
                const float* src = base + (size_t)(kind * 64 + d) * 16384 + ay * HW_ + hf * 4;
                u32 dst = sb + kind * 16384 + (((d << 6) + (ay << 3) + (hf << 2)) << 2);
                cpa16(dst, src);
            }
            CPA_COMMIT();
        }

        const int a = tid & 63;
        const int half_ = tid >> 6;
        const int d0 = half_ * 32;
        const int aoff = (a >> 3) * HW_ + (a & 7);

        // ---- v: 32 independent scalar LDGs into regs ----
        float vfr[32];
        #pragma unroll
        for (int i = 0; i < 32; i++)
            vfr[i] = base[(size_t)(128 + d0 + i) * 16384 + aoff];

        float frs[32];

        // ---- wait both groups once; q read phase ----
        CPA_WAIT(0);
        __syncthreads();
        {
            const float* st = (const float*)smem;
            #pragma unroll
            for (int i = 0; i < 32; i++) frs[i] = st[(d0 + i) * 64 + a];
        }
        __syncthreads();

        // ---- q write phase + k read phase ----
        {
            float ssq = 0.f;
            #pragma unroll
            for (int i = 0; i < 32; i += 2) {
                ssq += frs[i] * frs[i] + frs[i + 1] * frs[i + 1];
                u32 h_, l_;
                bfsplit2(frs[i], frs[i + 1], h_, l_);
                *(u32*)(smem + QH_O + SWZ(a, d0 + i)) = h_;
                *(u32*)(smem + QL_O + SWZ(a, d0 + i)) = l_;
            }
            psq[half_ * 64 + a] = ssq;
        }
        {
            const float* st = (const float*)(smem + 16384);
            #pragma unroll
            for (int i = 0; i < 32; i++) frs[i] = st[(d0 + i) * 64 + a];
        }
        __syncthreads();

        // ---- k write phase + v pack ----
        {
            float ssk = 0.f;
            #pragma unroll
            for (int i = 0; i < 32; i += 2) {
                ssk += frs[i] * frs[i] + frs[i + 1] * frs[i + 1];
                u32 h_, l_;
                bfsplit2(frs[i], frs[i + 1], h_, l_);
                *(u32*)(smem + KH_O + SWZ(a, d0 + i)) = h_;
                *(u32*)(smem + KL_O + SWZ(a, d0 + i)) = l_;
            }
            psk[half_ * 64 + a] = ssk;
        }
        #pragma unroll
        for (int i = 0; i < 32; i += 2)
            *(u32*)(smem + VH_O + SWZ(a, d0 + i)) = hpack2(vfr[i], vfr[i + 1]);
        __syncthreads();

        // ---- inverse norms ----
        if (tid < 64) {
            qsv[tid] = 1.0f / fmaxf(sqrtf(psq[tid] + psq[tid + 64]), 1e-12f);
        } else {
            int a2 = tid - 64;
            ksv[a2] = 1.0f / fmaxf(sqrtf(psk[a2] + psk[a2 + 64]), 1e-12f);
        }
        __syncthreads();

        const int m0 = wrp * 16;
        const int arow = m0 + (lane & 15);
        const int acol = (lane >> 4) * 8;
        const int bquad = ((lane >> 4) << 3) + (lane & 7);
        const int bkh_c = ((lane >> 3) & 1) * 8;

        const int r0 = m0 + (lane >> 2);
        const int cb = 2 * (lane & 3);

        // ---- prefetch bias fragments ----
        float2 bf0[8], bf1[8];
        {
            const float2* gb = (const float2*)(g_bias + head * 4096);
            #pragma unroll
            for (int j = 0; j < 8; j++) {
                bf0[j] = gb[r0 * 32 + j * 4 + (lane & 3)];
                bf1[j] = gb[(r0 + 8) * 32 + j * 4 + (lane & 3)];
            }
        }

        // ---- S = QK^T, 3-term bf16 ----
        float acc[8][4];
        #pragma unroll
        for (int j = 0; j < 8; j++)
            #pragma unroll
            for (int r = 0; r < 4; r++) acc[j][r] = 0.f;

        #pragma unroll
        for (int ks = 0; ks < 4; ks++) {
            const int kf = ks * 16;
            u32 aqh[4], aql[4];
            ldmx4(aqh, sb + QH_O + SWZ(arow, acol + kf));
            ldmx4(aql, sb + QL_O + SWZ(arow, acol + kf));
            #pragma unroll
            for (int j = 0; j < 8; j += 2) {
                u32 bkh[4], bkl[4];
                int krow = j * 8 + bquad;
                ldmx4(bkh, sb + KH_O + SWZ(krow, bkh_c + kf));
                ldmx4(bkl, sb + KL_O + SWZ(krow, bkh_c + kf));
                mma16816(acc[j], aqh, bkh);
                mma16816(acc[j], aqh, bkl);
                mma16816(acc[j], aql, bkh);
                mma16816(acc[j + 1], aqh, bkh + 2);
                mma16816(acc[j + 1], aqh, bkl + 2);
                mma16816(acc[j + 1], aql, bkh + 2);
            }
        }

        // ---- cosine scale + bias + softmax ----
        const float sc = __expf(fminf(lscale[head], 4.6051702f));
        const float f0 = sc * qsv[r0];
        const float f1 = sc * qsv[r0 + 8];
        #pragma unroll
        for (int j = 0; j < 8; j++) {
            int c = 8 * j + cb;
            float kc0 = ksv[c], kc1 = ksv[c + 1];
            acc[j][0] = acc[j][0] * f0 * kc0 + bf0[j].x;
            acc[j][1] = acc[j][1] * f0 * kc1 + bf0[j].y;
            acc[j][2] = acc[j][2] * f1 * kc0 + bf1[j].x;
            acc[j][3] = acc[j][3] * f1 * kc1 + bf1[j].y;
        }
        float mx0 = -1e30f, mx1 = -1e30f;
        #pragma unroll
        for (int j = 0; j < 8; j++) {
            mx0 = fmaxf(mx0, fmaxf(acc[j][0], acc[j][1]));
            mx1 = fmaxf(mx1, fmaxf(acc[j][2], acc[j][3]));
        }
        mx0 = fmaxf(mx0, __shfl_xor_sync(0xffffffffu, mx0, 1));
        mx0 = fmaxf(mx0, __shfl_xor_sync(0xffffffffu, mx0, 2));
        mx1 = fmaxf(mx1, __shfl_xor_sync(0xffffffffu, mx1, 1));
        mx1 = fmaxf(mx1, __shfl_xor_sync(0xffffffffu, mx1, 2));
        float s0 = 0.f, s1 = 0.f;
        #pragma unroll
        for (int j = 0; j < 8; j++) {
            acc[j][0] = __expf(acc[j][0] - mx0); s0 += acc[j][0];
            acc[j][1] = __expf(acc[j][1] - mx0); s0 += acc[j][1];
            acc[j][2] = __expf(acc[j][2] - mx1); s1 += acc[j][2];
            acc[j][3] = __expf(acc[j][3] - mx1); s1 += acc[j][3];
        }
        s0 += __shfl_xor_sync(0xffffffffu, s0, 1);
        s0 += __shfl_xor_sync(0xffffffffu, s0, 2);
        s1 += __shfl_xor_sync(0xffffffffu, s1, 1);
        s1 += __shfl_xor_sync(0xffffffffu, s1, 2);
        const float inv0 = 1.0f / s0, inv1 = 1.0f / s1;
        #pragma unroll
        for (int j = 0; j < 8; j++) {
            acc[j][0] *= inv0; acc[j][1] *= inv0;
            acc[j][2] *= inv1; acc[j][3] *= inv1;
        }

        // ---- repack P C-fragments as fp16 A-fragments ----
        u32 ap16[4][4];
        #pragma unroll
        for (int kk = 0; kk < 4; kk++) {
            ap16[kk][0] = hpack2(acc[2 * kk][0],     acc[2 * kk][1]);
            ap16[kk][1] = hpack2(acc[2 * kk][2],     acc[2 * kk][3]);
            ap16[kk][2] = hpack2(acc[2 * kk + 1][0], acc[2 * kk + 1][1]);
            ap16[kk][3] = hpack2(acc[2 * kk + 1][2], acc[2 * kk + 1][3]);
        }

        // ---- O = P.V, single-term fp16 ----
        float o[8][4];
        #pragma unroll
        for (int j = 0; j < 8; j++)
            #pragma unroll
            for (int r = 0; r < 4; r++) o[j][r] = 0.f;

        const int vrl = lane & 15;
        const int vdj = (lane >> 4) * 8;
        #pragma unroll
        for (int ks = 0; ks < 4; ks++) {
            const int kf = ks * 16;
            #pragma unroll
            for (int jd = 0; jd < 8; jd += 2) {
                u32 bv[4];
                ldmx4t(bv, sb + VH_O + SWZ(kf + vrl, jd * 8 + vdj));
                mma16816h(o[jd],     ap16[ks], bv);
                mma16816h(o[jd + 1], ap16[ks], bv + 2);
            }
        }

        // ---- store O as fp16 to X [pixel][channel] ----
        const int pr0 = b * 16384 + (wy * 8 + (r0 >> 3)) * HW_ + wx * 8 + (r0 & 7);
        const int r1 = r0 + 8;
        const int pr1 = b * 16384 + (wy * 8 + (r1 >> 3)) * HW_ + wx * 8 + (r1 & 7);
        const size_t x0 = (size_t)pr0 * CCH + head * 64;
        const size_t x1 = (size_t)pr1 * CCH + head * 64;
        #pragma unroll
        for (int j = 0; j < 8; j++) {
            int c = 8 * j + cb;
            *(u32*)(g_xh + x0 + c) = hpack2(o[j][0], o[j][1]);
            *(u32*)(g_xh + x1 + c) = hpack2(o[j][2], o[j][3]);
        }

        // ---- signal completion for this batch ----
        __syncthreads();
        __threadfence();
        if (tid == 0) atomicAdd(&g_ctr[b], 1u);

    } else {
        // ================= PROJECTION =================
        const int m0g = (pid & 3) * 128;
        const int n0g = (pid >> 2) * 64;
        const int bb  = n0g >> 14;

        // wait for all attn blocks of batch bb
        if (tid == 0) {
            while (atomicAdd(&g_ctr[bb], 0u) < 2048u) __nanosleep(512);
        }
        __syncthreads();
        __threadfence();

        const int wm = wrp >> 1;          // 0..1
        const int wn = wrp & 1;           // 0..1

        float acc[4][4][4];
        #pragma unroll
        for (int i = 0; i < 4; i++)
            #pragma unroll
            for (int j = 0; j < 4; j++)
                #pragma unroll
                for (int r = 0; r < 4; r++) acc[i][j][r] = 0.f;

        proj_load_stage3(sb,         m0g, n0g, 0,  tid);
        proj_load_stage3(sb + PSTG3, m0g, n0g, 32, tid);

        const int arow = wm * 64 + (lane & 15);
        const int acol = (lane >> 4) * 8;
        const int brow = wn * 32 + (lane & 7);
        const int bcol = ((lane >> 3) & 1) * 8;

        #pragma unroll 1
        for (int kc = 0; kc < 16; kc++) {
            const u32 stg = sb + (kc & 1) * PSTG3;
            if (kc < 15) { CPA_WAIT(1); } else { CPA_WAIT(0); }
            __syncthreads();

            const u32 whb = stg;
            const u32 xhb = stg + PW_B;

            #pragma unroll
            for (int ks = 0; ks < 2; ks++) {
                const int kf = ks * 16;
                u32 ah[4][4], bh[4][2];
                #pragma unroll
                for (int i = 0; i < 4; i++)
                    ldmx4(ah[i], whb + 2 * ((arow + i * 16) * LDT3 + acol + kf));
                #pragma unroll
                for (int j = 0; j < 4; j++)
                    ldmx2(bh[j], xhb + 2 * ((brow + j * 8) * LDT3 + bcol + kf));
                #pragma unroll
                for (int i = 0; i < 4; i++)
                    #pragma unroll
                    for (int j = 0; j < 4; j++)
                        mma16816h(acc[i][j], ah[i], bh[j]);
            }
            __syncthreads();
            if (kc + 2 < 16) proj_load_stage3(stg, m0g, n0g, (kc + 2) * 32, tid);
        }

        const int hwb = (n0g & 16383) + wn * 32 + 2 * (lane & 3);
        #pragma unroll
        for (int i = 0; i < 4; i++) {
            int m = m0g + wm * 64 + i * 16 + (lane >> 2);
            float bias0 = pb[m];
            float bias8 = pb[m + 8];
            float* r0p = out + ((size_t)(bb * CCH + m)) * 16384 + hwb;
            float* r8p = out + ((size_t)(bb * CCH + m + 8)) * 16384 + hwb;
            #pragma unroll
            for (int j = 0; j < 4; j++) {
                float2 v0 = {acc[i][j][0] + bias0, acc[i][j][1] + bias0};
                float2 v1 = {acc[i][j][2] + bias8, acc[i][j][3] + bias8};
                *(float2*)(r0p + j * 8) = v0;
                *(float2*)(r8p + j * 8) = v1;
            }
        }
    }
}

// ---------------------------------------------------------------------------
extern "C" void kernel_launch(void* const* d_in, const int* in_sizes, int n_in,
                              void* d_out, int out_size) {
    const float* qkv = (const float*)d_in[0];   // (4, 8, 192, 128, 128) f32
    const float* lsc = (const float*)d_in[1];   // (8,1,1) f32
    const float* rpb = (const float*)d_in[2];   // (225, 8) f32
    const float* pw  = (const float*)d_in[3];   // (512, 512) f32
    const float* pb  = (const float*)d_in[4];   // (512,) f32
    const int*   rel = (const int*)d_in[5];     // (64, 64) i32
    float* out = (float*)d_out;                 // (4, 512, 128, 128) f32

    cudaFuncSetAttribute(fused_kernel,
                         cudaFuncAttributeMaxDynamicSharedMemorySize, FUSED_SMEM);

    prep_kernel<<<(CCH * CCH + NHEAD * 64 * 64) / 256, 256>>>(pw, rpb, rel);
    fused_kernel<<<8192 + 4096, 128, FUSED_SMEM>>>(qkv, lsc, pb, out);
}

// round 17
// speedup vs baseline: 1.0571x; 1.0571x over previous
#include <cuda_runtime.h>
#include <cuda_bf16.h>
#include <cuda_fp16.h>
#include <cstdint>

// Problem constants (fixed shapes)
#define NHEAD 8
#define DH    64
#define HW_   128
#define NPIX  65536      // B*H*W
#define CCH   512        // channels

typedef unsigned long long u64;
typedef unsigned int u32;

// ---- scratch (allocation-free rule: __device__ globals) --------------------
__device__ __half g_xh[(size_t)NPIX * CCH];          // X (fp16), [pixel][channel]
__device__ __half g_w16[CCH * CCH];                  // W fp16, row-major [m][k]
__device__ float g_bias[NHEAD * 64 * 64];            // [head][q][k]

// ---- family-portable PTX helpers ------------------------------------------
__device__ __forceinline__ u32 smem_u32(const void* p) {
    u32 a; asm("{ .reg .u64 t; cvta.to.shared.u64 t, %1; cvt.u32.u64 %0, t; }"
               : "=r"(a) : "l"(p));
    return a;
}
__device__ __forceinline__ void cpa16(u32 dst, const void* src) {
    asm volatile("cp.async.cg.shared.global [%0], [%1], 16;" :: "r"(dst), "l"(src));
}
#define CPA_COMMIT() asm volatile("cp.async.commit_group;" ::: "memory")
#define CPA_WAIT(n)  asm volatile("cp.async.wait_group %0;" :: "n"(n) : "memory")

__device__ __forceinline__ void ldmx4(u32* r, u32 addr) {
    asm volatile("ldmatrix.sync.aligned.m8n8.x4.shared.b16 {%0,%1,%2,%3}, [%4];"
        : "=r"(r[0]), "=r"(r[1]), "=r"(r[2]), "=r"(r[3]) : "r"(addr));
}
__device__ __forceinline__ void ldmx2(u32* r, u32 addr) {
    asm volatile("ldmatrix.sync.aligned.m8n8.x2.shared.b16 {%0,%1}, [%2];"
        : "=r"(r[0]), "=r"(r[1]) : "r"(addr));
}
__device__ __forceinline__ void ldmx4t(u32* r, u32 addr) {
    asm volatile("ldmatrix.sync.aligned.m8n8.x4.trans.shared.b16 {%0,%1,%2,%3}, [%4];"
        : "=r"(r[0]), "=r"(r[1]), "=r"(r[2]), "=r"(r[3]) : "r"(addr));
}
// bf16 mma (attention QK)
__device__ __forceinline__ void mma16816(float* c, const u32* a, const u32* b) {
    asm volatile("mma.sync.aligned.m16n8k16.row.col.f32.bf16.bf16.f32 "
        "{%0,%1,%2,%3}, {%4,%5,%6,%7}, {%8,%9}, {%0,%1,%2,%3};"
        : "+f"(c[0]), "+f"(c[1]), "+f"(c[2]), "+f"(c[3])
        : "r"(a[0]), "r"(a[1]), "r"(a[2]), "r"(a[3]), "r"(b[0]), "r"(b[1]));
}
// fp16 mma (projection + attention PV)
__device__ __forceinline__ void mma16816h(float* c, const u32* a, const u32* b) {
    asm volatile("mma.sync.aligned.m16n8k16.row.col.f32.f16.f16.f32 "
        "{%0,%1,%2,%3}, {%4,%5,%6,%7}, {%8,%9}, {%0,%1,%2,%3};"
        : "+f"(c[0]), "+f"(c[1]), "+f"(c[2]), "+f"(c[3])
        : "r"(a[0]), "r"(a[1]), "r"(a[2]), "r"(a[3]), "r"(b[0]), "r"(b[1]));
}
// pack two fp32 -> bf16 pair (hi/lo split)
__device__ __forceinline__ void bfsplit2(float x0, float x1, u32& h, u32& l) {
    __nv_bfloat16 h0 = __float2bfloat16(x0);
    __nv_bfloat16 h1 = __float2bfloat16(x1);
    __nv_bfloat16 l0 = __float2bfloat16(x0 - __bfloat162float(h0));
    __nv_bfloat16 l1 = __float2bfloat16(x1 - __bfloat162float(h1));
    h = (u32)__bfloat16_as_ushort(h0) | ((u32)__bfloat16_as_ushort(h1) << 16);
    l = (u32)__bfloat16_as_ushort(l0) | ((u32)__bfloat16_as_ushort(l1) << 16);
}
// pack two fp32 -> fp16 pair
__device__ __forceinline__ u32 hpack2(float x0, float x1) {
    __half2 h = __floats2half2_rn(x0, x1);
    return *(u32*)&h;
}

// XOR-swizzled 64x64 b16 tile: row*128B, 8 chunks of 16B, chunk ^= row&7.
#define SWZ(row, col) (((row) << 7) + (((((col) >> 3) ^ (row)) & 7) << 4) + (((col) & 7) << 1))

// ---------------------------------------------------------------------------
// Kernel: fused prep — convert W to fp16 AND expand rpb bias table.
// ---------------------------------------------------------------------------
__global__ void __launch_bounds__(256) prep_kernel(const float* __restrict__ W,
                                                   const float* __restrict__ rpb,
                                                   const int* __restrict__ rel) {
    int idx = blockIdx.x * 256 + threadIdx.x;
    if (idx < CCH * CCH) {
        g_w16[idx] = __float2half_rn(W[idx]);
    } else {
        int i = idx - CCH * CCH;                    // 0..32767
        int h = i >> 12;
        int r = i & 4095;                           // q*64 + k
        g_bias[i] = rpb[rel[r] * NHEAD + h];
    }
}

// ---------------------------------------------------------------------------
// Kernel: windowed cosine attention. QK on bf16 3-term; PV on fp16 1-term.
// Block = one (window, head), 128 threads / 4 warps; warp w = query rows 16w..
// q,k via cp.async fp32 staging (overlaid by bf16 tiles); v via independent
// scalar LDGs into regs -> fp16 tile. Single wait + 5-barrier load phase.
// ---------------------------------------------------------------------------
// smem byte offsets
#define QH_O  0              // fp32 q staging = [0, 16384)
#define QL_O  8192
#define KH_O  16384          // fp32 k staging = [16384, 32768)
#define KL_O  24576
#define VH_O  32768          // fp16 V tile [a][d], 8KB (no staging)
#define PSQ_O 40960          // 128 floats
#define PSK_O 41472          // 128 floats
#define QSV_O 41984          // 64 floats: 1/|q_row|
#define KSV_O 42240          // 64 floats: 1/|k_row|
#define ATTN_SMEM 42496

__global__ void __launch_bounds__(128, 5) attn_kernel(const float* __restrict__ qkv,
                                                      const float* __restrict__ lscale) {
    extern __shared__ char smem[];
    float* psq  = (float*)(smem + PSQ_O);
    float* psk  = (float*)(smem + PSK_O);
    float* qsv  = (float*)(smem + QSV_O);
    float* ksv  = (float*)(smem + KSV_O);

    const int tid  = threadIdx.x;
    const int lane = tid & 31;
    const int wrp  = tid >> 5;

    const int wh   = blockIdx.x;
    const int head = wh & 7;
    const int win  = wh >> 3;
    const int b    = win >> 8;
    const int wy   = (win >> 4) & 15;
    const int wx   = win & 15;

    const float* base = qkv + (size_t)b * (NHEAD * 192 * 16384)
                            + (size_t)head * (192 * 16384)
                            + wy * 8 * HW_ + wx * 8;

    const u32 sb = smem_u32(smem);

    // ---- issue q,k as cp.async (2 groups) ----
    #pragma unroll
    for (int kind = 0; kind < 2; kind++) {
        #pragma unroll
        for (int j = 0; j < 8; j++) {
            int id = tid + j * 128;
            int d  = id >> 4;
            int ay = (id >> 1) & 7;
            int hf = id & 1;
            const float* src = base + (size_t)(kind * 64 + d) * 16384 + ay * HW_ + hf * 4;
            u32 dst = sb + kind * 16384 + (((d << 6) + (ay << 3) + (hf << 2)) << 2);
            cpa16(dst, src);
        }
        CPA_COMMIT();
    }

    const int a = tid & 63;
    const int half_ = tid >> 6;
    const int d0 = half_ * 32;
    const int aoff = (a >> 3) * HW_ + (a & 7);

    // ---- v: 32 independent scalar LDGs into regs (MLP 32) ----
    float vfr[32];
    #pragma unroll
    for (int i = 0; i < 32; i++)
        vfr[i] = base[(size_t)(128 + d0 + i) * 16384 + aoff];

    float frs[32];

    // ---- wait both groups once; q read phase ----
    CPA_WAIT(0);
    __syncthreads();
    {
        const float* st = (const float*)smem;
        #pragma unroll
        for (int i = 0; i < 32; i++) frs[i] = st[(d0 + i) * 64 + a];
    }
    __syncthreads();

    // ---- q write phase + k read phase (k staging untouched by q writes) ----
    {
        float ssq = 0.f;
        #pragma unroll
        for (int i = 0; i < 32; i += 2) {
            ssq += frs[i] * frs[i] + frs[i + 1] * frs[i + 1];
            u32 h_, l_;
            bfsplit2(frs[i], frs[i + 1], h_, l_);
            *(u32*)(smem + QH_O + SWZ(a, d0 + i)) = h_;
            *(u32*)(smem + QL_O + SWZ(a, d0 + i)) = l_;
        }
        psq[half_ * 64 + a] = ssq;
    }
    {
        const float* st = (const float*)(smem + 16384);
        #pragma unroll
        for (int i = 0; i < 32; i++) frs[i] = st[(d0 + i) * 64 + a];
    }
    __syncthreads();

    // ---- k write phase + v pack ----
    {
        float ssk = 0.f;
        #pragma unroll
        for (int i = 0; i < 32; i += 2) {
            ssk += frs[i] * frs[i] + frs[i + 1] * frs[i + 1];
            u32 h_, l_;
            bfsplit2(frs[i], frs[i + 1], h_, l_);
            *(u32*)(smem + KH_O + SWZ(a, d0 + i)) = h_;
            *(u32*)(smem + KL_O + SWZ(a, d0 + i)) = l_;
        }
        psk[half_ * 64 + a] = ssk;
    }
    #pragma unroll
    for (int i = 0; i < 32; i += 2)
        *(u32*)(smem + VH_O + SWZ(a, d0 + i)) = hpack2(vfr[i], vfr[i + 1]);
    __syncthreads();

    // ---- inverse norms ----
    if (tid < 64) {
        qsv[tid] = 1.0f / fmaxf(sqrtf(psq[tid] + psq[tid + 64]), 1e-12f);
    } else {
        int a2 = tid - 64;
        ksv[a2] = 1.0f / fmaxf(sqrtf(psk[a2] + psk[a2 + 64]), 1e-12f);
    }
    __syncthreads();

    const int m0 = wrp * 16;
    const int arow = m0 + (lane & 15);
    const int acol = (lane >> 4) * 8;
    // merged-x4 B addressing
    const int bquad = ((lane >> 4) << 3) + (lane & 7);
    const int bkh_c = ((lane >> 3) & 1) * 8;

    const int r0 = m0 + (lane >> 2);
    const int cb = 2 * (lane & 3);

    // ---- prefetch bias fragments (L2-resident; hides under QK MMAs) ----
    float2 bf0[8], bf1[8];
    {
        const float2* gb = (const float2*)(g_bias + head * 4096);
        #pragma unroll
        for (int j = 0; j < 8; j++) {
            bf0[j] = gb[r0 * 32 + j * 4 + (lane & 3)];
            bf1[j] = gb[(r0 + 8) * 32 + j * 4 + (lane & 3)];
        }
    }

    // ---- S = QK^T, 3-term bf16; K via merged ldmatrix.x4 ----
    float acc[8][4];
    #pragma unroll
    for (int j = 0; j < 8; j++)
        #pragma unroll
        for (int r = 0; r < 4; r++) acc[j][r] = 0.f;

    #pragma unroll
    for (int ks = 0; ks < 4; ks++) {
        const int kf = ks * 16;
        u32 aqh[4], aql[4];
        ldmx4(aqh, sb + QH_O + SWZ(arow, acol + kf));
        ldmx4(aql, sb + QL_O + SWZ(arow, acol + kf));
        #pragma unroll
        for (int j = 0; j < 8; j += 2) {
            u32 bkh[4], bkl[4];
            int krow = j * 8 + bquad;
            ldmx4(bkh, sb + KH_O + SWZ(krow, bkh_c + kf));
            ldmx4(bkl, sb + KL_O + SWZ(krow, bkh_c + kf));
            mma16816(acc[j], aqh, bkh);
            mma16816(acc[j], aqh, bkl);
            mma16816(acc[j], aql, bkh);
            mma16816(acc[j + 1], aqh, bkh + 2);
            mma16816(acc[j + 1], aqh, bkl + 2);
            mma16816(acc[j + 1], aql, bkh + 2);
        }
    }

    // ---- cosine scale + bias + softmax ----
    const float sc = __expf(fminf(lscale[head], 4.6051702f));
    const float f0 = sc * qsv[r0];
    const float f1 = sc * qsv[r0 + 8];
    #pragma unroll
    for (int j = 0; j < 8; j++) {
        int c = 8 * j + cb;
        float kc0 = ksv[c], kc1 = ksv[c + 1];
        acc[j][0] = acc[j][0] * f0 * kc0 + bf0[j].x;
        acc[j][1] = acc[j][1] * f0 * kc1 + bf0[j].y;
        acc[j][2] = acc[j][2] * f1 * kc0 + bf1[j].x;
        acc[j][3] = acc[j][3] * f1 * kc1 + bf1[j].y;
    }
    float mx0 = -1e30f, mx1 = -1e30f;
    #pragma unroll
    for (int j = 0; j < 8; j++) {
        mx0 = fmaxf(mx0, fmaxf(acc[j][0], acc[j][1]));
        mx1 = fmaxf(mx1, fmaxf(acc[j][2], acc[j][3]));
    }
    mx0 = fmaxf(mx0, __shfl_xor_sync(0xffffffffu, mx0, 1));
    mx0 = fmaxf(mx0, __shfl_xor_sync(0xffffffffu, mx0, 2));
    mx1 = fmaxf(mx1, __shfl_xor_sync(0xffffffffu, mx1, 1));
    mx1 = fmaxf(mx1, __shfl_xor_sync(0xffffffffu, mx1, 2));
    float s0 = 0.f, s1 = 0.f;
    #pragma unroll
    for (int j = 0; j < 8; j++) {
        acc[j][0] = __expf(acc[j][0] - mx0); s0 += acc[j][0];
        acc[j][1] = __expf(acc[j][1] - mx0); s0 += acc[j][1];
        acc[j][2] = __expf(acc[j][2] - mx1); s1 += acc[j][2];
        acc[j][3] = __expf(acc[j][3] - mx1); s1 += acc[j][3];
    }
    s0 += __shfl_xor_sync(0xffffffffu, s0, 1);
    s0 += __shfl_xor_sync(0xffffffffu, s0, 2);
    s1 += __shfl_xor_sync(0xffffffffu, s1, 1);
    s1 += __shfl_xor_sync(0xffffffffu, s1, 2);
    const float inv0 = 1.0f / s0, inv1 = 1.0f / s1;
    #pragma unroll
    for (int j = 0; j < 8; j++) {
        acc[j][0] *= inv0; acc[j][1] *= inv0;
        acc[j][2] *= inv1; acc[j][3] *= inv1;
    }

    // ---- repack P C-fragments as fp16 A-fragments ----
    u32 ap16[4][4];
    #pragma unroll
    for (int kk = 0; kk < 4; kk++) {
        ap16[kk][0] = hpack2(acc[2 * kk][0],     acc[2 * kk][1]);
        ap16[kk][1] = hpack2(acc[2 * kk][2],     acc[2 * kk][3]);
        ap16[kk][2] = hpack2(acc[2 * kk + 1][0], acc[2 * kk + 1][1]);
        ap16[kk][3] = hpack2(acc[2 * kk + 1][2], acc[2 * kk + 1][3]);
    }

    // ---- O = P.V, single-term fp16; V [a][d] via merged ldmatrix.x4.trans ----
    float o[8][4];
    #pragma unroll
    for (int j = 0; j < 8; j++)
        #pragma unroll
        for (int r = 0; r < 4; r++) o[j][r] = 0.f;

    const int vrl = lane & 15;
    const int vdj = (lane >> 4) * 8;
    #pragma unroll
    for (int ks = 0; ks < 4; ks++) {
        const int kf = ks * 16;
        #pragma unroll
        for (int jd = 0; jd < 8; jd += 2) {
            u32 bv[4];
            ldmx4t(bv, sb + VH_O + SWZ(kf + vrl, jd * 8 + vdj));
            mma16816h(o[jd],     ap16[ks], bv);
            mma16816h(o[jd + 1], ap16[ks], bv + 2);
        }
    }

    // ---- store O as fp16 to X [pixel][channel] ----
    const int pr0 = b * 16384 + (wy * 8 + (r0 >> 3)) * HW_ + wx * 8 + (r0 & 7);
    const int r1 = r0 + 8;
    const int pr1 = b * 16384 + (wy * 8 + (r1 >> 3)) * HW_ + wx * 8 + (r1 & 7);
    const size_t x0 = (size_t)pr0 * CCH + head * 64;
    const size_t x1 = (size_t)pr1 * CCH + head * 64;
    #pragma unroll
    for (int j = 0; j < 8; j++) {
        int c = 8 * j + cb;
        *(u32*)(g_xh + x0 + c) = hpack2(o[j][0], o[j][1]);
        *(u32*)(g_xh + x1 + c) = hpack2(o[j][2], o[j][3]);
    }
}

// ---------------------------------------------------------------------------
// Kernel: projection GEMM via mma.sync fp16, single term (W16 · X16).
// CTA: 128 channels (M) x 128 pixels (N), K=512 in 8 chunks of 64.
// (R10/R13 configuration — 2-stage pipeline, ldmx2 B — measured 115.2us floor.)
// ---------------------------------------------------------------------------
#define LDT2 72                      // 64 + 8 pad (fp16 units)
#define PTILE_B (128 * LDT2 * 2)     // 18432 bytes per tile
#define PSTG_B  (2 * PTILE_B)        // W | X = 36864
#define PROJ_SMEM (2 * PSTG_B)       // 73728 bytes

__device__ __forceinline__ void proj_load_stage(u32 sbase, int m0g, int n0g, int k0, int tid) {
    #pragma unroll
    for (int j = 0; j < 4; j++) {
        int id = tid + j * 256;          // 0..1023
        int r  = id >> 3;                // row 0..127
        int c  = (id & 7) * 8;           // col (fp16)
        u32 dst = sbase + 2 * (r * LDT2 + c);
        cpa16(dst,           g_w16 + (size_t)(m0g + r) * CCH + k0 + c);
        cpa16(dst + PTILE_B, g_xh  + (size_t)(n0g + r) * CCH + k0 + c);
    }
    CPA_COMMIT();
}

__global__ void __launch_bounds__(256) proj_hmma_kernel(const float* __restrict__ pb,
                                                        float* __restrict__ out) {
    extern __shared__ __half psm[];
    const int tid  = threadIdx.x;
    const int wid  = tid >> 5;
    const int lane = tid & 31;
    const int wm   = wid >> 2;
    const int wn   = wid & 3;

    const int m0g = blockIdx.x * 128;
    const int n0g = blockIdx.y * 128;

    const u32 sb = smem_u32(psm);

    float acc[4][4][4];
    #pragma unroll
    for (int i = 0; i < 4; i++)
        #pragma unroll
        for (int j = 0; j < 4; j++)
            #pragma unroll
            for (int r = 0; r < 4; r++) acc[i][j][r] = 0.f;

    proj_load_stage(sb,          m0g, n0g, 0,  tid);
    proj_load_stage(sb + PSTG_B, m0g, n0g, 64, tid);

    const int arow = wm * 64 + (lane & 15);
    const int acol = (lane >> 4) * 8;
    const int brow = wn * 32 + (lane & 7);
    const int bcol = ((lane >> 3) & 1) * 8;

    #pragma unroll 1
    for (int kc = 0; kc < 8; kc++) {
        const u32 stg = sb + (kc & 1) * PSTG_B;
        if (kc < 7) { CPA_WAIT(1); } else { CPA_WAIT(0); }
        __syncthreads();

        const u32 whb = stg;
        const u32 xhb = stg + PTILE_B;

        #pragma unroll
        for (int ks = 0; ks < 4; ks++) {
            const int kf = ks * 16;
            u32 ah[4][4], bh[4][2];
            #pragma unroll
            for (int i = 0; i < 4; i++)
                ldmx4(ah[i], whb + 2 * ((arow + i * 16) * LDT2 + acol + kf));
            #pragma unroll
            for (int j = 0; j < 4; j++)
                ldmx2(bh[j], xhb + 2 * ((brow + j * 8) * LDT2 + bcol + kf));
            #pragma unroll
            for (int i = 0; i < 4; i++)
                #pragma unroll
                for (int j = 0; j < 4; j++)
                    mma16816h(acc[i][j], ah[i], bh[j]);
        }
        __syncthreads();
        if (kc + 2 < 8) proj_load_stage(stg, m0g, n0g, (kc + 2) * 64, tid);
    }

    const int bb = n0g >> 14;
    const int hwb = (n0g & 16383) + wn * 32 + 2 * (lane & 3);
    #pragma unroll
    for (int i = 0; i < 4; i++) {
        int m = m0g + wm * 64 + i * 16 + (lane >> 2);
        float bias0 = pb[m];
        float bias8 = pb[m + 8];
        float* r0 = out + ((size_t)(bb * CCH + m)) * 16384 + hwb;
        float* r8 = out + ((size_t)(bb * CCH + m + 8)) * 16384 + hwb;
        #pragma unroll
        for (int j = 0; j < 4; j++) {
            float2 v0 = {acc[i][j][0] + bias0, acc[i][j][1] + bias0};
            float2 v1 = {acc[i][j][2] + bias8, acc[i][j][3] + bias8};
            *(float2*)(r0 + j * 8) = v0;
            *(float2*)(r8 + j * 8) = v1;
        }
    }
}

// ---------------------------------------------------------------------------
extern "C" void kernel_launch(void* const* d_in, const int* in_sizes, int n_in,
                              void* d_out, int out_size) {
    const float* qkv = (const float*)d_in[0];   // (4, 8, 192, 128, 128) f32
    const float* lsc = (const float*)d_in[1];   // (8,1,1) f32
    const float* rpb = (const float*)d_in[2];   // (225, 8) f32
    const float* pw  = (const float*)d_in[3];   // (512, 512) f32
    const float* pb  = (const float*)d_in[4];   // (512,) f32
    const int*   rel = (const int*)d_in[5];     // (64, 64) i32
    float* out = (float*)d_out;                 // (4, 512, 128, 128) f32

    cudaFuncSetAttribute(attn_kernel,
                         cudaFuncAttributeMaxDynamicSharedMemorySize, ATTN_SMEM);
    cudaFuncSetAttribute(proj_hmma_kernel,
                         cudaFuncAttributeMaxDynamicSharedMemorySize, PROJ_SMEM);

    prep_kernel<<<(CCH * CCH + NHEAD * 64 * 64) / 256, 256>>>(pw, rpb, rel);
    attn_kernel<<<1024 * NHEAD, 128, ATTN_SMEM>>>(qkv, lsc);
    proj_hmma_kernel<<<dim3(CCH / 128, NPIX / 128), 256, PROJ_SMEM>>>(pb, out);
}